// round 15
// baseline (speedup 1.0000x reference)
#include <cuda_runtime.h>
#include <cstdint>
#include <cstddef>

// ---------------- problem constants ----------------
#define B_  8
#define N_  2048
#define DE  1024
#define DR  512

// ---------------- GEMM tiling ----------------
#define BM 128
#define BN 64
#define BK 32
#define STAGES 3
#define SLOT_WORDS ((BM + BN) * BK)           // 6144 words = 24 KB
#define SMEM_GEMM (STAGES * SLOT_WORDS * 4)   // 73728 B -> 3 CTAs/SM

// ---------------- scratch (device globals: allocation-guard safe) -----
static __device__ __align__(1024) float g_q [(size_t)B_ * N_ * DR];
static __device__ __align__(1024) float g_k [(size_t)B_ * N_ * DR];
static __device__ __align__(1024) float g_v [(size_t)B_ * N_ * DR];
static __device__ __align__(1024) float g_vt[(size_t)B_ * DR * N_];   // V^T: [b][d][t]
static __device__ __align__(1024) float g_wt[(size_t)2 * DR * DE];    // W^T: [w][n][k]
static __device__ __align__(1024) float g_s [(size_t)B_ * N_ * N_];

extern __shared__ uint32_t dyn_smem[];

// ---------------- helpers ----------------
__device__ __forceinline__ uint32_t f2tf(float x) {
    uint32_t u;
    asm("cvt.rna.tf32.f32 %0, %1;" : "=r"(u) : "f"(x));
    return u;
}
__device__ __forceinline__ float rnd_tf(float x) { return __uint_as_float(f2tf(x)); }

__device__ __forceinline__ uint32_t smem_u32(const void* p) {
    uint32_t a;
    asm("{ .reg .u64 t; cvta.to.shared.u64 t, %1; cvt.u32.u64 %0, t; }" : "=r"(a) : "l"(p));
    return a;
}

__device__ __forceinline__ void mma_tf32(float* c, const uint32_t* a, const uint32_t* b) {
    asm volatile(
        "mma.sync.aligned.m16n8k8.row.col.f32.tf32.tf32.f32 "
        "{%0,%1,%2,%3},{%4,%5,%6,%7},{%8,%9},{%0,%1,%2,%3};"
        : "+f"(c[0]), "+f"(c[1]), "+f"(c[2]), "+f"(c[3])
        : "r"(a[0]), "r"(a[1]), "r"(a[2]), "r"(a[3]), "r"(b[0]), "r"(b[1]));
}

#define CP_ASYNC16(dst, src) \
    asm volatile("cp.async.cg.shared.global [%0], [%1], 16;" :: "r"(dst), "l"(src))
#define CP_COMMIT() asm volatile("cp.async.commit_group;")
#define CP_WAIT(n)  asm volatile("cp.async.wait_group %0;" :: "n"(n))

// -------------------- GEMM core -------------------------------------------
// C[M,N] (+)= A[M,K] * B^T where B is [N,K], K-contiguous rows.
// B must be pre-rounded to tf32 (rna). A: if RNA_A, A is raw f32 and is staged
// via LDG -> cvt.rna -> STS; else A must be pre-rounded, staged via cp.async.
// Block tile 128x64xBK32, 256 threads: 8 warps in 4(M) x 2(N), warp tile 32x32.
// 3 CTAs/SM (72 KB smem, 85 regs): 24 warps/SM hides the per-tile pipeline
// window that bound the 2-CTA/64x32 configuration.
// SMEM: m-major rows of 32 tf32 (128B), XOR swizzle on 16B chunks:
//   word(m,k) = m*32 + ((k>>2) ^ (m&7))*4 + (k&3)
// -> conflict-free fill AND conflict-free scalar LDS fragment loads.
// 3-stage cp.async ring; single fragment buffer.
__device__ __forceinline__ void ldfrag(
    uint32_t (&af)[2][4], uint32_t (&bf)[4][2],
    const uint32_t* as, const uint32_t* bs,
    const int (&pa)[2], const int (&pb)[4], int g, int c0)
{
    const int x0 = ((c0 ^ g) << 2);
    const int x1 = (((c0 + 1) ^ g) << 2);
    #pragma unroll
    for (int mf = 0; mf < 2; ++mf) {
        af[mf][0] = as[pa[mf] + x0];
        af[mf][1] = as[pa[mf] + 8 * BK + x0];
        af[mf][2] = as[pa[mf] + x1];
        af[mf][3] = as[pa[mf] + 8 * BK + x1];
    }
    #pragma unroll
    for (int nf = 0; nf < 4; ++nf) {
        bf[nf][0] = bs[pb[nf] + x0];
        bf[nf][1] = bs[pb[nf] + x1];
    }
}

template <bool RNA_A>
__device__ __forceinline__ void gemm_core(
    const float* __restrict__ A, const float* __restrict__ B,
    int lda, int ldb, int ktiles, int m0, int n0,
    float (&acc)[2][4][4])
{
    const int tid  = threadIdx.x;
    const int lane = tid & 31;
    const int warp = tid >> 5;
    const int wm = (warp & 3) * 32;        // 4 warps over M=128
    const int wn = (warp >> 2) * 32;       // 2 warps over N=64
    const int g = lane >> 2;               // 0..7
    const int r = lane & 3;                // 0..3
    const uint32_t smb = smem_u32(dyn_smem);

    // ---- staging: A 4 chunks, B 2 chunks per thread ----
    const float* srcA[4];
    const float* srcB[2];
    uint32_t dstA[4], dstB[2];
    #pragma unroll
    for (int i = 0; i < 4; ++i) {
        const int ci = tid + 256 * i;           // 0..1023
        const int m = ci >> 3, c = ci & 7;
        srcA[i] = A + (size_t)(m0 + m) * lda + (c << 2);
        dstA[i] = (uint32_t)(m * BK + ((c ^ (m & 7)) << 2)) * 4;
    }
    #pragma unroll
    for (int i = 0; i < 2; ++i) {
        const int ci = tid + 256 * i;           // 0..511
        const int m = ci >> 3, c = ci & 7;
        srcB[i] = B + (size_t)(n0 + m) * ldb + (c << 2);
        dstB[i] = (uint32_t)(m * BK + ((c ^ (m & 7)) << 2)) * 4;
    }

    int pa[2], pb[4];
    #pragma unroll
    for (int mf = 0; mf < 2; ++mf) pa[mf] = (wm + mf * 16 + g) * BK + r;
    #pragma unroll
    for (int nf = 0; nf < 4; ++nf) pb[nf] = (wn + nf * 8 + g) * BK + r;

    float4 aR[4];                   // used only when RNA_A
    if (RNA_A) {
        #pragma unroll
        for (int i = 0; i < 4; ++i) aR[i] = *(const float4*)srcA[i];
    }
    #pragma unroll
    for (int s = 0; s < STAGES - 1; ++s) {
        if (s < ktiles) {
            const uint32_t ab = smb + (uint32_t)(s * SLOT_WORDS) * 4;
            const uint32_t bb = ab + BM * BK * 4;
            const int kk = s * BK;
            if (!RNA_A) {
                #pragma unroll
                for (int i = 0; i < 4; ++i) CP_ASYNC16(ab + dstA[i], srcA[i] + kk);
            }
            #pragma unroll
            for (int i = 0; i < 2; ++i) CP_ASYNC16(bb + dstB[i], srcB[i] + kk);
        }
        CP_COMMIT();
    }

    int slot = 0;
    int rslot = STAGES - 1;
    for (int t = 0; t < ktiles; ++t) {
        CP_WAIT(STAGES - 2);

        // RNA_A: stage A tile t (rna tf32) into current slot before the barrier.
        if (RNA_A) {
            uint32_t* slotA = dyn_smem + slot * SLOT_WORDS;
            #pragma unroll
            for (int i = 0; i < 4; ++i)
                *(uint4*)((char*)slotA + dstA[i]) =
                    make_uint4(f2tf(aR[i].x), f2tf(aR[i].y), f2tf(aR[i].z), f2tf(aR[i].w));
        }
        __syncthreads();

        // refill slot for tile t+2; always commit (uniform counts at tail)
        {
            const int tn = t + STAGES - 1;
            if (tn < ktiles) {
                const uint32_t ab = smb + (uint32_t)(rslot * SLOT_WORDS) * 4;
                const uint32_t bb = ab + BM * BK * 4;
                const int kk = tn * BK;
                if (!RNA_A) {
                    #pragma unroll
                    for (int i = 0; i < 4; ++i) CP_ASYNC16(ab + dstA[i], srcA[i] + kk);
                }
                #pragma unroll
                for (int i = 0; i < 2; ++i) CP_ASYNC16(bb + dstB[i], srcB[i] + kk);
            }
            CP_COMMIT();
        }

        if (RNA_A && (t + 1 < ktiles)) {
            const int kk = (t + 1) * BK;
            #pragma unroll
            for (int i = 0; i < 4; ++i) aR[i] = *(const float4*)(srcA[i] + kk);
        }

        const uint32_t* as = dyn_smem + slot * SLOT_WORDS;
        const uint32_t* bs = as + BM * BK;

        // 4 k-slices of 8
        #pragma unroll
        for (int s = 0; s < 4; ++s) {
            uint32_t af[2][4], bf[4][2];
            ldfrag(af, bf, as, bs, pa, pb, g, 2 * s);
            #pragma unroll
            for (int mf = 0; mf < 2; ++mf)
                #pragma unroll
                for (int nf = 0; nf < 4; ++nf)
                    mma_tf32(acc[mf][nf], af[mf], bf[nf]);
        }

        if (++slot == STAGES) slot = 0;
        if (++rslot == STAGES) rslot = 0;
    }
}

__device__ __forceinline__ void zero_acc(float (&acc)[2][4][4]) {
    #pragma unroll
    for (int i = 0; i < 2; ++i)
        #pragma unroll
        for (int j = 0; j < 4; ++j)
            #pragma unroll
            for (int l = 0; l < 4; ++l) acc[i][j][l] = 0.0f;
}

__device__ __forceinline__ void store_acc(
    float* O, int ldo, int m0, int n0, const float (&acc)[2][4][4])
{
    const int lane = threadIdx.x & 31;
    const int warp = threadIdx.x >> 5;
    const int wm = (warp & 3) * 32;
    const int wn = (warp >> 2) * 32;
    #pragma unroll
    for (int mf = 0; mf < 2; ++mf)
        #pragma unroll
        for (int nf = 0; nf < 4; ++nf) {
            const int rr = m0 + wm + mf * 16 + (lane >> 2);
            const int cc = n0 + wn + nf * 8 + ((lane & 3) << 1);
            *(float2*)(O + (size_t)rr * ldo + cc)       = make_float2(acc[mf][nf][0], acc[mf][nf][1]);
            *(float2*)(O + (size_t)(rr + 8) * ldo + cc) = make_float2(acc[mf][nf][2], acc[mf][nf][3]);
        }
}

// -------------------- device bodies ---------------------------------------
// projection body: z=0 -> q, z=1 -> k, z=2 -> v  (outputs rna tf32)
__device__ __forceinline__ void proj_body(
    int z, int m0, int n0,
    const float* __restrict__ x0, const float* __restrict__ x1, const float* __restrict__ x2,
    const float* __restrict__ bq, const float* __restrict__ bk)
{
    const float* X    = (z == 0) ? x0 : ((z == 1) ? x1 : x2);
    const float* W    = g_wt + (size_t)((z == 0) ? 0 : 1) * DR * DE;
    const float* bias = (z == 0) ? bq : bk;
    float* O          = (z == 0) ? g_q : ((z == 1) ? g_k : g_v);
    const float scale = (z == 0) ? 0.04419417382415922f : 1.0f;   // 1/sqrt(512)

    float acc[2][4][4];
    zero_acc(acc);
    gemm_core<true>(X, W, DE, DE, DE / BK, m0, n0, acc);   // A raw: rna at STS

    const int lane = threadIdx.x & 31;
    const int warp = threadIdx.x >> 5;
    const int wm = (warp & 3) * 32;
    const int wn = (warp >> 2) * 32;
    #pragma unroll
    for (int mf = 0; mf < 2; ++mf)
        #pragma unroll
        for (int nf = 0; nf < 4; ++nf) {
            const int rr = m0 + wm + mf * 16 + (lane >> 2);
            const int cc = n0 + wn + nf * 8 + ((lane & 3) << 1);
            const float b0 = bias[cc], b1 = bias[cc + 1];
            *(float2*)(O + (size_t)rr * DR + cc) =
                make_float2(rnd_tf((acc[mf][nf][0] + b0) * scale),
                            rnd_tf((acc[mf][nf][1] + b1) * scale));
            *(float2*)(O + (size_t)(rr + 8) * DR + cc) =
                make_float2(rnd_tf((acc[mf][nf][2] + b0) * scale),
                            rnd_tf((acc[mf][nf][3] + b1) * scale));
        }
}

// scores body: S = Q K^T for one (b, m0, n0) tile
__device__ __forceinline__ void scores_body(int b, int m0, int n0)
{
    const float* Q  = g_q + (size_t)b * N_ * DR;
    const float* Km = g_k + (size_t)b * N_ * DR;
    float* S        = g_s + (size_t)b * N_ * N_;

    float acc[2][4][4];
    zero_acc(acc);
    gemm_core<false>(Q, Km, DR, DR, DR / BK, m0, n0, acc);
    store_acc(S, N_, m0, n0, acc);
}

// V transpose body ([t][d] -> [d][t])
__device__ __forceinline__ void transv_body(int b, int t0, int d0)
{
    __shared__ float t[32][33];
    const float* I = g_v  + (size_t)b * N_ * DR;
    float*       O = g_vt + (size_t)b * DR * N_;
    const int tx = threadIdx.x & 31, ty = threadIdx.x >> 5;
    #pragma unroll
    for (int i = 0; i < 4; ++i)
        t[ty + 8 * i][tx] = I[(size_t)(t0 + ty + 8 * i) * DR + d0 + tx];
    __syncthreads();
    #pragma unroll
    for (int i = 0; i < 4; ++i)
        O[(size_t)(d0 + ty + 8 * i) * N_ + t0 + tx] = t[tx][ty + 8 * i];   // already tf32
}

// ---- softmax pieces ----
__device__ __forceinline__ float fast_exp(float x) {
    float t = fmaxf(x * 1.4426950408889634f, -126.0f);
    float fi = floorf(t);
    float f = t - fi;
    float p = fmaf(0.00015403530393381608f, f, 0.0013333558146428443f);
    p = fmaf(p, f, 0.009618129107628477f);
    p = fmaf(p, f, 0.05550410866482158f);
    p = fmaf(p, f, 0.24022650695910072f);
    p = fmaf(p, f, 0.6931471805599453f);
    p = fmaf(p, f, 1.0f);
    return p * __int_as_float((uint32_t)((int)fi + 127) << 23);
}
__device__ __forceinline__ float brmax(float v) {
    __shared__ float sm[8];
    #pragma unroll
    for (int o = 16; o > 0; o >>= 1) v = fmaxf(v, __shfl_xor_sync(0xffffffffu, v, o));
    if ((threadIdx.x & 31) == 0) sm[threadIdx.x >> 5] = v;
    __syncthreads();
    v = sm[0];
    #pragma unroll
    for (int i = 1; i < 8; ++i) v = fmaxf(v, sm[i]);
    __syncthreads();
    return v;
}
__device__ __forceinline__ float brsum(float v) {
    __shared__ float sm2[8];
    #pragma unroll
    for (int o = 16; o > 0; o >>= 1) v += __shfl_xor_sync(0xffffffffu, v, o);
    if ((threadIdx.x & 31) == 0) sm2[threadIdx.x >> 5] = v;
    __syncthreads();
    v = sm2[0];
    #pragma unroll
    for (int i = 1; i < 8; ++i) v += sm2[i];
    __syncthreads();
    return v;
}

// causal row softmax (in-place, rna out). rows < 1024 skip chunk 1 (see r13).
__device__ __forceinline__ void softmax_body(int row)
{
    const int rr  = row & (N_ - 1);
    float* S = g_s + (size_t)row * N_;
    const int tid = threadIdx.x;
    const int valid = rr + 1;
    const int nchunk = (rr >= 1024) ? 2 : 1;

    float v[8];
    float lmax = -3.402823466e38f;
    for (int i = 0; i < nchunk; ++i) {
        const int c = (tid + i * 256) << 2;
        float4 f = *(const float4*)(S + c);
        v[i * 4 + 0] = (c + 0 < valid) ? f.x : -3.402823466e38f;
        v[i * 4 + 1] = (c + 1 < valid) ? f.y : -3.402823466e38f;
        v[i * 4 + 2] = (c + 2 < valid) ? f.z : -3.402823466e38f;
        v[i * 4 + 3] = (c + 3 < valid) ? f.w : -3.402823466e38f;
        lmax = fmaxf(lmax, fmaxf(fmaxf(v[i*4], v[i*4+1]), fmaxf(v[i*4+2], v[i*4+3])));
    }
    const float m = brmax(lmax);

    float lsum = 0.0f;
    for (int i = 0; i < nchunk * 4; ++i) {
        const int c = ((tid + (i >> 2) * 256) << 2) + (i & 3);
        float e = (c < valid) ? fast_exp(v[i] - m) : 0.0f;
        v[i] = e;
        lsum += e;
    }
    const float inv = 1.0f / brsum(lsum);

    for (int i = 0; i < nchunk; ++i) {
        const int c = (tid + i * 256) << 2;
        *(float4*)(S + c) = make_float4(rnd_tf(v[i*4] * inv), rnd_tf(v[i*4+1] * inv),
                                        rnd_tf(v[i*4+2] * inv), rnd_tf(v[i*4+3] * inv));
    }
}

// -------------------- kernels ---------------------------------------------
// W transpose ([k][n] -> [n][k], rna tf32)
__global__ void __launch_bounds__(256) trans_w(
    const float* __restrict__ Wq, const float* __restrict__ Wk)
{
    __shared__ float t[32][33];
    const int w = blockIdx.z;
    const float* W = w ? Wk : Wq;
    float* O = g_wt + (size_t)w * DR * DE;
    const int n0 = blockIdx.x * 32, k0 = blockIdx.y * 32;
    const int tx = threadIdx.x & 31, ty = threadIdx.x >> 5;    // 32 x 8
    #pragma unroll
    for (int i = 0; i < 4; ++i)
        t[ty + 8 * i][tx] = W[(size_t)(k0 + ty + 8 * i) * DR + n0 + tx];
    __syncthreads();
    #pragma unroll
    for (int i = 0; i < 4; ++i)
        O[(size_t)(n0 + ty + 8 * i) * DE + k0 + tx] = rnd_tf(t[tx][ty + 8 * i]);
}

// proj for q and k only (z = blockIdx.z in {0,1}) — the only predecessor of scores
__global__ void __launch_bounds__(256, 3) proj_qk_kernel(
    const float* __restrict__ x0, const float* __restrict__ x1,
    const float* __restrict__ bq, const float* __restrict__ bk)
{
    proj_body(blockIdx.z, blockIdx.y * BM, blockIdx.x * BN, x0, x1, nullptr, bq, bk);
}

// fused: proj_v (first 1024 blocks) || scores (next 4096 blocks, causal skip).
#define PV_BLOCKS 1024
__global__ void __launch_bounds__(256, 3) fused_sv_kernel(
    const float* __restrict__ x2,
    const float* __restrict__ bq, const float* __restrict__ bk)
{
    const int bid = blockIdx.x;
    if (bid < PV_BLOCKS) {
        const int m0 = (bid >> 3) * BM;        // 128 m-blocks
        const int n0 = (bid & 7) * BN;         // 8 n-blocks
        proj_body(2, m0, n0, nullptr, nullptr, x2, bq, bk);
    } else {
        const int t = bid - PV_BLOCKS;         // 0..4095
        const int b = t >> 9;                  // 8 batches, 512 tiles each
        const int r = t & 511;                 // 16(m) x 32(n)
        const int m0 = (r >> 5) * BM;
        const int n0 = (r & 31) * BN;
        if (n0 >= m0 + BM) return;             // above diagonal: masked by softmax
        scores_body(b, m0, n0);
    }
}

// fused: softmax (first 16384 blocks) || V transpose (next 8192 blocks)
#define SM_BLOCKS (B_ * N_)
__global__ void __launch_bounds__(256) fused_smtv_kernel()
{
    const int bid = blockIdx.x;
    if (bid < SM_BLOCKS) {
        softmax_body(bid);
    } else {
        const int t = bid - SM_BLOCKS;         // 0..8191 = 64 x 16 x 8
        const int t0 = (t & 63) * 32;
        const int d0 = ((t >> 6) & 15) * 32;
        const int b  = t >> 10;
        transv_body(b, t0, d0);
    }
}

// out = P @ V with causal k truncation
__global__ void __launch_bounds__(256, 3) out_kernel(float* __restrict__ out)
{
    const int b  = blockIdx.z;
    const int m0 = blockIdx.y * BM;
    const int n0 = blockIdx.x * BN;

    const float* S  = g_s  + (size_t)b * N_ * N_;
    const float* Vt = g_vt + (size_t)b * DR * N_;
    const int ktiles = (m0 + BM) / BK;   // cols > m0+127 are all zero after softmax

    float acc[2][4][4];
    zero_acc(acc);
    gemm_core<false>(S, Vt, N_, N_, ktiles, m0, n0, acc);
    store_acc(out + (size_t)b * N_ * DR, DR, m0, n0, acc);
}

// -------------------- launch ----------------------------------------------
extern "C" void kernel_launch(void* const* d_in, const int* in_sizes, int n_in,
                              void* d_out, int out_size)
{
    (void)in_sizes; (void)n_in; (void)out_size;
    const float* x0 = (const float*)d_in[0];
    const float* x1 = (const float*)d_in[1];
    const float* x2 = (const float*)d_in[2];
    const float* Wq = (const float*)d_in[3];
    const float* bq = (const float*)d_in[4];
    const float* Wk = (const float*)d_in[5];
    const float* bk = (const float*)d_in[6];
    float* out = (float*)d_out;

    static bool attr_done = false;
    if (!attr_done) {
        cudaFuncSetAttribute(proj_qk_kernel,  cudaFuncAttributeMaxDynamicSharedMemorySize, SMEM_GEMM);
        cudaFuncSetAttribute(fused_sv_kernel, cudaFuncAttributeMaxDynamicSharedMemorySize, SMEM_GEMM);
        cudaFuncSetAttribute(out_kernel,      cudaFuncAttributeMaxDynamicSharedMemorySize, SMEM_GEMM);
        attr_done = true;
    }

    dim3 blk(256);
    trans_w<<<dim3(DR / 32, DE / 32, 2), blk>>>(Wq, Wk);
    proj_qk_kernel<<<dim3(DR / BN, (B_ * N_) / BM, 2), blk, SMEM_GEMM>>>(x0, x1, bq, bk);
    fused_sv_kernel<<<dim3(PV_BLOCKS + 4096), blk, SMEM_GEMM>>>(x2, bq, bk);
    fused_smtv_kernel<<<dim3(SM_BLOCKS + 8192), blk>>>();
    out_kernel<<<dim3(DR / BN, N_ / BM, B_), blk, SMEM_GEMM>>>(out);
}

// round 16
// speedup vs baseline: 1.3344x; 1.3344x over previous
#include <cuda_runtime.h>
#include <cstdint>
#include <cstddef>

// ---------------- problem constants ----------------
#define B_  8
#define N_  2048
#define DE  1024
#define DR  512

// ---------------- GEMM tiling ----------------
#define BM 128
#define BN 128
#define BK 32
#define STAGES 3
#define SLOT_WORDS ((BM + BN) * BK)           // 8192 words = 32 KB
#define SMEM_GEMM (STAGES * SLOT_WORDS * 4)   // 98304 B -> 2 CTAs/SM

// ---------------- scratch (device globals: allocation-guard safe) -----
static __device__ __align__(1024) float g_q [(size_t)B_ * N_ * DR];
static __device__ __align__(1024) float g_k [(size_t)B_ * N_ * DR];
static __device__ __align__(1024) float g_v [(size_t)B_ * N_ * DR];
static __device__ __align__(1024) float g_vt[(size_t)B_ * DR * N_];   // V^T: [b][d][t]
static __device__ __align__(1024) float g_wt[(size_t)2 * DR * DE];    // W^T: [w][n][k]
static __device__ __align__(1024) float g_s [(size_t)B_ * N_ * N_];

extern __shared__ uint32_t dyn_smem[];

// ---------------- helpers ----------------
__device__ __forceinline__ uint32_t f2tf(float x) {
    uint32_t u;
    asm("cvt.rna.tf32.f32 %0, %1;" : "=r"(u) : "f"(x));
    return u;
}
__device__ __forceinline__ float rnd_tf(float x) { return __uint_as_float(f2tf(x)); }

__device__ __forceinline__ uint32_t smem_u32(const void* p) {
    uint32_t a;
    asm("{ .reg .u64 t; cvta.to.shared.u64 t, %1; cvt.u32.u64 %0, t; }" : "=r"(a) : "l"(p));
    return a;
}

__device__ __forceinline__ void mma_tf32(float* c, const uint32_t* a, const uint32_t* b) {
    asm volatile(
        "mma.sync.aligned.m16n8k8.row.col.f32.tf32.tf32.f32 "
        "{%0,%1,%2,%3},{%4,%5,%6,%7},{%8,%9},{%0,%1,%2,%3};"
        : "+f"(c[0]), "+f"(c[1]), "+f"(c[2]), "+f"(c[3])
        : "r"(a[0]), "r"(a[1]), "r"(a[2]), "r"(a[3]), "r"(b[0]), "r"(b[1]));
}

#define CP_ASYNC16(dst, src) \
    asm volatile("cp.async.cg.shared.global [%0], [%1], 16;" :: "r"(dst), "l"(src))
#define CP_COMMIT() asm volatile("cp.async.commit_group;")
#define CP_WAIT(n)  asm volatile("cp.async.wait_group %0;" :: "n"(n))

// -------------------- GEMM core (r13/r14 proven engine) --------------------
// C[M,N] (+)= A[M,K] * B^T where B is [N,K], K-contiguous rows.
// B must be pre-rounded to tf32 (rna). A: if RNA_A, A is raw f32 and is staged
// via LDG -> cvt.rna -> STS; else A must be pre-rounded, staged via cp.async.
// Block tile 128x128xBK32, 256 threads: 8 warps in 2(M) x 4(N), warp tile 64x32.
// 2 CTAs/SM (96 KB smem, 128 regs). SW128-style XOR swizzle:
//   word(m,k) = m*32 + ((k>>2) ^ (m&7))*4 + (k&3)  -> conflict-free fill + LDS.
// 3-stage cp.async ring; single fragment buffer.
__device__ __forceinline__ void ldfrag(
    uint32_t (&af)[4][4], uint32_t (&bf)[4][2],
    const uint32_t* as, const uint32_t* bs,
    const int (&pa)[4], const int (&pb)[4], int g, int c0)
{
    const int x0 = ((c0 ^ g) << 2);
    const int x1 = (((c0 + 1) ^ g) << 2);
    #pragma unroll
    for (int mf = 0; mf < 4; ++mf) {
        af[mf][0] = as[pa[mf] + x0];
        af[mf][1] = as[pa[mf] + 8 * BK + x0];
        af[mf][2] = as[pa[mf] + x1];
        af[mf][3] = as[pa[mf] + 8 * BK + x1];
    }
    #pragma unroll
    for (int nf = 0; nf < 4; ++nf) {
        bf[nf][0] = bs[pb[nf] + x0];
        bf[nf][1] = bs[pb[nf] + x1];
    }
}

template <bool RNA_A>
__device__ __forceinline__ void gemm_core(
    const float* __restrict__ A, const float* __restrict__ B,
    int lda, int ldb, int ktiles, int m0, int n0,
    float (&acc)[4][4][4])
{
    const int tid  = threadIdx.x;
    const int lane = tid & 31;
    const int warp = tid >> 5;
    const int wm = (warp & 1) * 64;
    const int wn = (warp >> 1) * 32;
    const int g = lane >> 2;        // 0..7
    const int r = lane & 3;         // 0..3
    const uint32_t smb = smem_u32(dyn_smem);

    const float* srcA[4];
    const float* srcB[4];
    uint32_t dstb[4];
    #pragma unroll
    for (int i = 0; i < 4; ++i) {
        const int ci = tid + 256 * i;           // 0..1023
        const int m = ci >> 3, c = ci & 7;
        srcA[i] = A + (size_t)(m0 + m) * lda + (c << 2);
        srcB[i] = B + (size_t)(n0 + m) * ldb + (c << 2);
        dstb[i] = (uint32_t)(m * BK + ((c ^ (m & 7)) << 2)) * 4;
    }

    int pa[4], pb[4];
    #pragma unroll
    for (int mf = 0; mf < 4; ++mf) pa[mf] = (wm + mf * 16 + g) * BK + r;
    #pragma unroll
    for (int nf = 0; nf < 4; ++nf) pb[nf] = (wn + nf * 8 + g) * BK + r;

    float4 aR[4];                   // used only when RNA_A
    if (RNA_A) {
        #pragma unroll
        for (int i = 0; i < 4; ++i) aR[i] = *(const float4*)srcA[i];
    }
    #pragma unroll
    for (int s = 0; s < STAGES - 1; ++s) {
        if (s < ktiles) {
            const uint32_t ab = smb + (uint32_t)(s * SLOT_WORDS) * 4;
            const uint32_t bb = ab + BM * BK * 4;
            const int kk = s * BK;
            if (!RNA_A) {
                #pragma unroll
                for (int i = 0; i < 4; ++i) CP_ASYNC16(ab + dstb[i], srcA[i] + kk);
            }
            #pragma unroll
            for (int i = 0; i < 4; ++i) CP_ASYNC16(bb + dstb[i], srcB[i] + kk);
        }
        CP_COMMIT();
    }

    int slot = 0;
    int rslot = STAGES - 1;
    for (int t = 0; t < ktiles; ++t) {
        CP_WAIT(STAGES - 2);

        if (RNA_A) {
            uint32_t* slotA = dyn_smem + slot * SLOT_WORDS;
            #pragma unroll
            for (int i = 0; i < 4; ++i)
                *(uint4*)((char*)slotA + dstb[i]) =
                    make_uint4(f2tf(aR[i].x), f2tf(aR[i].y), f2tf(aR[i].z), f2tf(aR[i].w));
        }
        __syncthreads();

        {
            const int tn = t + STAGES - 1;
            if (tn < ktiles) {
                const uint32_t ab = smb + (uint32_t)(rslot * SLOT_WORDS) * 4;
                const uint32_t bb = ab + BM * BK * 4;
                const int kk = tn * BK;
                if (!RNA_A) {
                    #pragma unroll
                    for (int i = 0; i < 4; ++i) CP_ASYNC16(ab + dstb[i], srcA[i] + kk);
                }
                #pragma unroll
                for (int i = 0; i < 4; ++i) CP_ASYNC16(bb + dstb[i], srcB[i] + kk);
            }
            CP_COMMIT();
        }

        if (RNA_A && (t + 1 < ktiles)) {
            const int kk = (t + 1) * BK;
            #pragma unroll
            for (int i = 0; i < 4; ++i) aR[i] = *(const float4*)(srcA[i] + kk);
        }

        const uint32_t* as = dyn_smem + slot * SLOT_WORDS;
        const uint32_t* bs = as + BM * BK;

        #pragma unroll
        for (int s = 0; s < 4; ++s) {
            uint32_t af[4][4], bf[4][2];
            ldfrag(af, bf, as, bs, pa, pb, g, 2 * s);
            #pragma unroll
            for (int mf = 0; mf < 4; ++mf)
                #pragma unroll
                for (int nf = 0; nf < 4; ++nf)
                    mma_tf32(acc[mf][nf], af[mf], bf[nf]);
        }

        if (++slot == STAGES) slot = 0;
        if (++rslot == STAGES) rslot = 0;
    }
}

__device__ __forceinline__ void zero_acc(float (&acc)[4][4][4]) {
    #pragma unroll
    for (int i = 0; i < 4; ++i)
        #pragma unroll
        for (int j = 0; j < 4; ++j)
            #pragma unroll
            for (int l = 0; l < 4; ++l) acc[i][j][l] = 0.0f;
}

__device__ __forceinline__ void store_acc(
    float* O, int ldo, int m0, int n0, const float (&acc)[4][4][4])
{
    const int lane = threadIdx.x & 31;
    const int warp = threadIdx.x >> 5;
    const int wm = (warp & 1) * 64;
    const int wn = (warp >> 1) * 32;
    #pragma unroll
    for (int mf = 0; mf < 4; ++mf)
        #pragma unroll
        for (int nf = 0; nf < 4; ++nf) {
            const int rr = m0 + wm + mf * 16 + (lane >> 2);
            const int cc = n0 + wn + nf * 8 + ((lane & 3) << 1);
            *(float2*)(O + (size_t)rr * ldo + cc)       = make_float2(acc[mf][nf][0], acc[mf][nf][1]);
            *(float2*)(O + (size_t)(rr + 8) * ldo + cc) = make_float2(acc[mf][nf][2], acc[mf][nf][3]);
        }
}

// -------------------- device bodies ---------------------------------------
__device__ __forceinline__ void proj_body(
    int z, int m0, int n0,
    const float* __restrict__ x0, const float* __restrict__ x1, const float* __restrict__ x2,
    const float* __restrict__ bq, const float* __restrict__ bk)
{
    const float* X    = (z == 0) ? x0 : ((z == 1) ? x1 : x2);
    const float* W    = g_wt + (size_t)((z == 0) ? 0 : 1) * DR * DE;
    const float* bias = (z == 0) ? bq : bk;
    float* O          = (z == 0) ? g_q : ((z == 1) ? g_k : g_v);
    const float scale = (z == 0) ? 0.04419417382415922f : 1.0f;   // 1/sqrt(512)

    float acc[4][4][4];
    zero_acc(acc);
    gemm_core<true>(X, W, DE, DE, DE / BK, m0, n0, acc);   // A raw: rna at STS

    const int lane = threadIdx.x & 31;
    const int warp = threadIdx.x >> 5;
    const int wm = (warp & 1) * 64;
    const int wn = (warp >> 1) * 32;
    #pragma unroll
    for (int mf = 0; mf < 4; ++mf)
        #pragma unroll
        for (int nf = 0; nf < 4; ++nf) {
            const int rr = m0 + wm + mf * 16 + (lane >> 2);
            const int cc = n0 + wn + nf * 8 + ((lane & 3) << 1);
            const float b0 = bias[cc], b1 = bias[cc + 1];
            *(float2*)(O + (size_t)rr * DR + cc) =
                make_float2(rnd_tf((acc[mf][nf][0] + b0) * scale),
                            rnd_tf((acc[mf][nf][1] + b1) * scale));
            *(float2*)(O + (size_t)(rr + 8) * DR + cc) =
                make_float2(rnd_tf((acc[mf][nf][2] + b0) * scale),
                            rnd_tf((acc[mf][nf][3] + b1) * scale));
        }
}

__device__ __forceinline__ void scores_body(int b, int m0, int n0)
{
    const float* Q  = g_q + (size_t)b * N_ * DR;
    const float* Km = g_k + (size_t)b * N_ * DR;
    float* S        = g_s + (size_t)b * N_ * N_;

    float acc[4][4][4];
    zero_acc(acc);
    gemm_core<false>(Q, Km, DR, DR, DR / BK, m0, n0, acc);
    store_acc(S, N_, m0, n0, acc);
}

__device__ __forceinline__ void transv_body(int b, int t0, int d0)
{
    __shared__ float t[32][33];
    const float* I = g_v  + (size_t)b * N_ * DR;
    float*       O = g_vt + (size_t)b * DR * N_;
    const int tx = threadIdx.x & 31, ty = threadIdx.x >> 5;
    #pragma unroll
    for (int i = 0; i < 4; ++i)
        t[ty + 8 * i][tx] = I[(size_t)(t0 + ty + 8 * i) * DR + d0 + tx];
    __syncthreads();
    #pragma unroll
    for (int i = 0; i < 4; ++i)
        O[(size_t)(d0 + ty + 8 * i) * N_ + t0 + tx] = t[tx][ty + 8 * i];   // already tf32
}

// ---- softmax pieces ----
__device__ __forceinline__ float fast_exp(float x) {
    float t = fmaxf(x * 1.4426950408889634f, -126.0f);
    float fi = floorf(t);
    float f = t - fi;
    float p = fmaf(0.00015403530393381608f, f, 0.0013333558146428443f);
    p = fmaf(p, f, 0.009618129107628477f);
    p = fmaf(p, f, 0.05550410866482158f);
    p = fmaf(p, f, 0.24022650695910072f);
    p = fmaf(p, f, 0.6931471805599453f);
    p = fmaf(p, f, 1.0f);
    return p * __int_as_float((uint32_t)((int)fi + 127) << 23);
}
__device__ __forceinline__ float brmax(float v) {
    __shared__ float sm[8];
    #pragma unroll
    for (int o = 16; o > 0; o >>= 1) v = fmaxf(v, __shfl_xor_sync(0xffffffffu, v, o));
    if ((threadIdx.x & 31) == 0) sm[threadIdx.x >> 5] = v;
    __syncthreads();
    v = sm[0];
    #pragma unroll
    for (int i = 1; i < 8; ++i) v = fmaxf(v, sm[i]);
    __syncthreads();
    return v;
}
__device__ __forceinline__ float brsum(float v) {
    __shared__ float sm2[8];
    #pragma unroll
    for (int o = 16; o > 0; o >>= 1) v += __shfl_xor_sync(0xffffffffu, v, o);
    if ((threadIdx.x & 31) == 0) sm2[threadIdx.x >> 5] = v;
    __syncthreads();
    v = sm2[0];
    #pragma unroll
    for (int i = 1; i < 8; ++i) v += sm2[i];
    __syncthreads();
    return v;
}

// causal row softmax (in-place, rna out). rows < 1024 skip chunk 1 (see r13).
__device__ __forceinline__ void softmax_body(int row)
{
    const int rr  = row & (N_ - 1);
    float* S = g_s + (size_t)row * N_;
    const int tid = threadIdx.x;
    const int valid = rr + 1;
    const int nchunk = (rr >= 1024) ? 2 : 1;

    float v[8];
    float lmax = -3.402823466e38f;
    for (int i = 0; i < nchunk; ++i) {
        const int c = (tid + i * 256) << 2;
        float4 f = *(const float4*)(S + c);
        v[i * 4 + 0] = (c + 0 < valid) ? f.x : -3.402823466e38f;
        v[i * 4 + 1] = (c + 1 < valid) ? f.y : -3.402823466e38f;
        v[i * 4 + 2] = (c + 2 < valid) ? f.z : -3.402823466e38f;
        v[i * 4 + 3] = (c + 3 < valid) ? f.w : -3.402823466e38f;
        lmax = fmaxf(lmax, fmaxf(fmaxf(v[i*4], v[i*4+1]), fmaxf(v[i*4+2], v[i*4+3])));
    }
    const float m = brmax(lmax);

    float lsum = 0.0f;
    for (int i = 0; i < nchunk * 4; ++i) {
        const int c = ((tid + (i >> 2) * 256) << 2) + (i & 3);
        float e = (c < valid) ? fast_exp(v[i] - m) : 0.0f;
        v[i] = e;
        lsum += e;
    }
    const float inv = 1.0f / brsum(lsum);

    for (int i = 0; i < nchunk; ++i) {
        const int c = (tid + i * 256) << 2;
        *(float4*)(S + c) = make_float4(rnd_tf(v[i*4] * inv), rnd_tf(v[i*4+1] * inv),
                                        rnd_tf(v[i*4+2] * inv), rnd_tf(v[i*4+3] * inv));
    }
}

// -------------------- kernels ---------------------------------------------
// W transpose ([k][n] -> [n][k], rna tf32)
__global__ void __launch_bounds__(256) trans_w(
    const float* __restrict__ Wq, const float* __restrict__ Wk)
{
    __shared__ float t[32][33];
    const int w = blockIdx.z;
    const float* W = w ? Wk : Wq;
    float* O = g_wt + (size_t)w * DR * DE;
    const int n0 = blockIdx.x * 32, k0 = blockIdx.y * 32;
    const int tx = threadIdx.x & 31, ty = threadIdx.x >> 5;    // 32 x 8
    #pragma unroll
    for (int i = 0; i < 4; ++i)
        t[ty + 8 * i][tx] = W[(size_t)(k0 + ty + 8 * i) * DR + n0 + tx];
    __syncthreads();
    #pragma unroll
    for (int i = 0; i < 4; ++i)
        O[(size_t)(n0 + ty + 8 * i) * DE + k0 + tx] = rnd_tf(t[tx][ty + 8 * i]);
}

// proj for q and k only (z = blockIdx.z in {0,1}) — the only predecessor of scores
__global__ void __launch_bounds__(256, 2) proj_qk_kernel(
    const float* __restrict__ x0, const float* __restrict__ x1,
    const float* __restrict__ bq, const float* __restrict__ bk)
{
    proj_body(blockIdx.z, blockIdx.y * BM, blockIdx.x * BN, x0, x1, nullptr, bq, bk);
}

// fused: proj_v (first 512 blocks) || scores (next 2048, causal skip,
// heavy m-tiles first so wave-1 carries the big work and light tiles backfill).
#define PV_BLOCKS 512
__global__ void __launch_bounds__(256, 2) fused_sv_kernel(
    const float* __restrict__ x2,
    const float* __restrict__ bq, const float* __restrict__ bk)
{
    const int bid = blockIdx.x;
    if (bid < PV_BLOCKS) {
        const int m0 = (bid >> 2) * BM;        // 128 m-blocks
        const int n0 = (bid & 3) * BN;         // 4 n-blocks
        proj_body(2, m0, n0, nullptr, nullptr, x2, bq, bk);
    } else {
        const int t = bid - PV_BLOCKS;         // 0..2047
        const int b = t >> 8;                  // 8 batches
        const int r = t & 255;                 // 16x16 tiles
        const int m0 = (15 - (r >> 4)) * BM;   // heavy (large-m) tiles first
        const int n0 = (r & 15) * BN;
        if (n0 > m0) return;                   // above diagonal: masked by softmax
        scores_body(b, m0, n0);
    }
}

// fused: softmax (first 16384 blocks) || V transpose (next 8192 blocks)
#define SM_BLOCKS (B_ * N_)
__global__ void __launch_bounds__(256) fused_smtv_kernel()
{
    const int bid = blockIdx.x;
    if (bid < SM_BLOCKS) {
        softmax_body(bid);
    } else {
        const int t = bid - SM_BLOCKS;         // 0..8191 = 64 x 16 x 8
        const int t0 = (t & 63) * 32;
        const int d0 = ((t >> 6) & 15) * 32;
        const int b  = t >> 10;
        transv_body(b, t0, d0);
    }
}

// out = P @ V with causal k truncation; heavy (large-ktiles) m-tiles first.
__global__ void __launch_bounds__(256, 2) out_kernel(float* __restrict__ out)
{
    const int b  = blockIdx.z;
    const int mt = gridDim.y - 1 - blockIdx.y;   // descending m0: big work first
    const int m0 = mt * BM;
    const int n0 = blockIdx.x * BN;

    const float* S  = g_s  + (size_t)b * N_ * N_;
    const float* Vt = g_vt + (size_t)b * DR * N_;
    const int ktiles = (m0 + BM) / BK;   // cols > m0+127 are all zero after softmax

    float acc[4][4][4];
    zero_acc(acc);
    gemm_core<false>(S, Vt, N_, N_, ktiles, m0, n0, acc);
    store_acc(out + (size_t)b * N_ * DR, DR, m0, n0, acc);
}

// -------------------- launch ----------------------------------------------
extern "C" void kernel_launch(void* const* d_in, const int* in_sizes, int n_in,
                              void* d_out, int out_size)
{
    (void)in_sizes; (void)n_in; (void)out_size;
    const float* x0 = (const float*)d_in[0];
    const float* x1 = (const float*)d_in[1];
    const float* x2 = (const float*)d_in[2];
    const float* Wq = (const float*)d_in[3];
    const float* bq = (const float*)d_in[4];
    const float* Wk = (const float*)d_in[5];
    const float* bk = (const float*)d_in[6];
    float* out = (float*)d_out;

    static bool attr_done = false;
    if (!attr_done) {
        cudaFuncSetAttribute(proj_qk_kernel,  cudaFuncAttributeMaxDynamicSharedMemorySize, SMEM_GEMM);
        cudaFuncSetAttribute(fused_sv_kernel, cudaFuncAttributeMaxDynamicSharedMemorySize, SMEM_GEMM);
        cudaFuncSetAttribute(out_kernel,      cudaFuncAttributeMaxDynamicSharedMemorySize, SMEM_GEMM);
        attr_done = true;
    }

    dim3 blk(256);
    trans_w<<<dim3(DR / 32, DE / 32, 2), blk>>>(Wq, Wk);
    proj_qk_kernel<<<dim3(DR / BN, (B_ * N_) / BM, 2), blk, SMEM_GEMM>>>(x0, x1, bq, bk);
    fused_sv_kernel<<<dim3(PV_BLOCKS + 2048), blk, SMEM_GEMM>>>(x2, bq, bk);
    fused_smtv_kernel<<<dim3(SM_BLOCKS + 8192), blk>>>();
    out_kernel<<<dim3(DR / BN, N_ / BM, B_), blk, SMEM_GEMM>>>(out);
}

// round 17
// speedup vs baseline: 1.6417x; 1.2302x over previous
#include <cuda_runtime.h>
#include <cuda_fp16.h>
#include <cstdint>
#include <cstddef>

// ---------------- problem constants ----------------
#define B_  8
#define N_  2048
#define DE  1024
#define DR  512

// ---------------- GEMM tiling ----------------
#define BM 128
#define BN 128
#define BK 32                                  // f32 engine: 32 f32 = 128B rows
#define BKH 64                                 // fp16 engine: 64 halves = 128B rows
#define STAGES 3
#define SLOT_WORDS ((BM + BN) * BK)            // 8192 words = 32 KB (same bytes both engines)
#define SMEM_GEMM (STAGES * SLOT_WORDS * 4)    // 98304 B -> 2 CTAs/SM

// ---------------- scratch (device globals: allocation-guard safe) -----
static __device__ __align__(1024) __half g_q [(size_t)B_ * N_ * DR];
static __device__ __align__(1024) __half g_k [(size_t)B_ * N_ * DR];
static __device__ __align__(1024) __half g_v [(size_t)B_ * N_ * DR];
static __device__ __align__(1024) __half g_vt[(size_t)B_ * DR * N_];  // V^T: [b][d][t]
static __device__ __align__(1024) float  g_wt[(size_t)2 * DR * DE];   // W^T f32 (tf32 rna)
static __device__ __align__(1024) float  g_s [(size_t)B_ * N_ * N_];  // scores f32
static __device__ __align__(1024) __half g_p [(size_t)B_ * N_ * N_];  // softmax(P) fp16

extern __shared__ uint32_t dyn_smem[];

// ---------------- helpers ----------------
__device__ __forceinline__ uint32_t f2tf(float x) {
    uint32_t u;
    asm("cvt.rna.tf32.f32 %0, %1;" : "=r"(u) : "f"(x));
    return u;
}
__device__ __forceinline__ float rnd_tf(float x) { return __uint_as_float(f2tf(x)); }

__device__ __forceinline__ uint32_t smem_u32(const void* p) {
    uint32_t a;
    asm("{ .reg .u64 t; cvta.to.shared.u64 t, %1; cvt.u32.u64 %0, t; }" : "=r"(a) : "l"(p));
    return a;
}

__device__ __forceinline__ void mma_tf32(float* c, const uint32_t* a, const uint32_t* b) {
    asm volatile(
        "mma.sync.aligned.m16n8k8.row.col.f32.tf32.tf32.f32 "
        "{%0,%1,%2,%3},{%4,%5,%6,%7},{%8,%9},{%0,%1,%2,%3};"
        : "+f"(c[0]), "+f"(c[1]), "+f"(c[2]), "+f"(c[3])
        : "r"(a[0]), "r"(a[1]), "r"(a[2]), "r"(a[3]), "r"(b[0]), "r"(b[1]));
}

__device__ __forceinline__ void mma_f16(float* c, const uint32_t* a, const uint32_t* b) {
    asm volatile(
        "mma.sync.aligned.m16n8k16.row.col.f32.f16.f16.f32 "
        "{%0,%1,%2,%3},{%4,%5,%6,%7},{%8,%9},{%0,%1,%2,%3};"
        : "+f"(c[0]), "+f"(c[1]), "+f"(c[2]), "+f"(c[3])
        : "r"(a[0]), "r"(a[1]), "r"(a[2]), "r"(a[3]), "r"(b[0]), "r"(b[1]));
}

#define CP_ASYNC16(dst, src) \
    asm volatile("cp.async.cg.shared.global [%0], [%1], 16;" :: "r"(dst), "l"(src))
#define CP_COMMIT() asm volatile("cp.async.commit_group;")
#define CP_WAIT(n)  asm volatile("cp.async.wait_group %0;" :: "n"(n))

// -------------------- shared fragment loader ------------------------------
// SMEM layout (both engines): m-major rows of 128B (32 words), XOR swizzle on
// 16B chunks: word(m, chunk c, word w) = m*32 + ((c ^ (m&7))<<2) + w.
// f32 engine: word = one tf32 (k = c*4+w). fp16 engine: word = half pair
// (k = c*8 + 2w + {0,1}). Fragment index math is IDENTICAL.
__device__ __forceinline__ void ldfrag(
    uint32_t (&af)[4][4], uint32_t (&bf)[4][2],
    const uint32_t* as, const uint32_t* bs,
    const int (&pa)[4], const int (&pb)[4], int g, int c0)
{
    const int x0 = ((c0 ^ g) << 2);
    const int x1 = (((c0 + 1) ^ g) << 2);
    #pragma unroll
    for (int mf = 0; mf < 4; ++mf) {
        af[mf][0] = as[pa[mf] + x0];
        af[mf][1] = as[pa[mf] + 8 * 32 + x0];
        af[mf][2] = as[pa[mf] + x1];
        af[mf][3] = as[pa[mf] + 8 * 32 + x1];
    }
    #pragma unroll
    for (int nf = 0; nf < 4; ++nf) {
        bf[nf][0] = bs[pb[nf] + x0];
        bf[nf][1] = bs[pb[nf] + x1];
    }
}

// -------------------- f32/tf32 GEMM engine (proj only; RNA A staging) ------
__device__ __forceinline__ void gemm_core_f32(
    const float* __restrict__ A, const float* __restrict__ B,
    int lda, int ldb, int ktiles, int m0, int n0,
    float (&acc)[4][4][4])
{
    const int tid  = threadIdx.x;
    const int lane = tid & 31;
    const int warp = tid >> 5;
    const int wm = (warp & 1) * 64;
    const int wn = (warp >> 1) * 32;
    const int g = lane >> 2;
    const int r = lane & 3;
    const uint32_t smb = smem_u32(dyn_smem);

    const float* srcA[4];
    const float* srcB[4];
    uint32_t dstb[4];
    #pragma unroll
    for (int i = 0; i < 4; ++i) {
        const int ci = tid + 256 * i;
        const int m = ci >> 3, c = ci & 7;
        srcA[i] = A + (size_t)(m0 + m) * lda + (c << 2);
        srcB[i] = B + (size_t)(n0 + m) * ldb + (c << 2);
        dstb[i] = (uint32_t)(m * 32 + ((c ^ (m & 7)) << 2)) * 4;
    }

    int pa[4], pb[4];
    #pragma unroll
    for (int mf = 0; mf < 4; ++mf) pa[mf] = (wm + mf * 16 + g) * 32 + r;
    #pragma unroll
    for (int nf = 0; nf < 4; ++nf) pb[nf] = (wn + nf * 8 + g) * 32 + r;

    float4 aR[4];
    #pragma unroll
    for (int i = 0; i < 4; ++i) aR[i] = *(const float4*)srcA[i];

    #pragma unroll
    for (int s = 0; s < STAGES - 1; ++s) {
        if (s < ktiles) {
            const uint32_t ab = smb + (uint32_t)(s * SLOT_WORDS) * 4;
            const uint32_t bb = ab + BM * 32 * 4;
            const int kk = s * BK;
            #pragma unroll
            for (int i = 0; i < 4; ++i) CP_ASYNC16(bb + dstb[i], srcB[i] + kk);
        }
        CP_COMMIT();
    }

    int slot = 0;
    int rslot = STAGES - 1;
    for (int t = 0; t < ktiles; ++t) {
        CP_WAIT(STAGES - 2);

        // stage A tile t (rna tf32) into current slot before the barrier
        {
            uint32_t* slotA = dyn_smem + slot * SLOT_WORDS;
            #pragma unroll
            for (int i = 0; i < 4; ++i)
                *(uint4*)((char*)slotA + dstb[i]) =
                    make_uint4(f2tf(aR[i].x), f2tf(aR[i].y), f2tf(aR[i].z), f2tf(aR[i].w));
        }
        __syncthreads();

        {
            const int tn = t + STAGES - 1;
            if (tn < ktiles) {
                const uint32_t ab = smb + (uint32_t)(rslot * SLOT_WORDS) * 4;
                const uint32_t bb = ab + BM * 32 * 4;
                const int kk = tn * BK;
                #pragma unroll
                for (int i = 0; i < 4; ++i) CP_ASYNC16(bb + dstb[i], srcB[i] + kk);
            }
            CP_COMMIT();
        }

        if (t + 1 < ktiles) {
            const int kk = (t + 1) * BK;
            #pragma unroll
            for (int i = 0; i < 4; ++i) aR[i] = *(const float4*)(srcA[i] + kk);
        }

        const uint32_t* as = dyn_smem + slot * SLOT_WORDS;
        const uint32_t* bs = as + BM * 32;

        #pragma unroll
        for (int s = 0; s < 4; ++s) {
            uint32_t af[4][4], bf[4][2];
            ldfrag(af, bf, as, bs, pa, pb, g, 2 * s);
            #pragma unroll
            for (int mf = 0; mf < 4; ++mf)
                #pragma unroll
                for (int nf = 0; nf < 4; ++nf)
                    mma_tf32(acc[mf][nf], af[mf], bf[nf]);
        }

        if (++slot == STAGES) slot = 0;
        if (++rslot == STAGES) rslot = 0;
    }
}

// -------------------- fp16 GEMM engine (scores, out) -----------------------
// C[M,N] (+)= A[M,K] * B^T, A/B fp16 with K-contiguous rows, f32 accumulate.
// BKH=64 halves per k-tile (128B rows). Same smem bytes / swizzle / frag math.
__device__ __forceinline__ void gemm_core_h(
    const __half* __restrict__ A, const __half* __restrict__ B,
    int lda, int ldb, int ktiles, int m0, int n0,
    float (&acc)[4][4][4])
{
    const int tid  = threadIdx.x;
    const int lane = tid & 31;
    const int warp = tid >> 5;
    const int wm = (warp & 1) * 64;
    const int wn = (warp >> 1) * 32;
    const int g = lane >> 2;
    const int r = lane & 3;
    const uint32_t smb = smem_u32(dyn_smem);

    const __half* srcA[4];
    const __half* srcB[4];
    uint32_t dstb[4];
    #pragma unroll
    for (int i = 0; i < 4; ++i) {
        const int ci = tid + 256 * i;
        const int m = ci >> 3, c = ci & 7;      // chunk = 8 halves = 16B
        srcA[i] = A + (size_t)(m0 + m) * lda + (c << 3);
        srcB[i] = B + (size_t)(n0 + m) * ldb + (c << 3);
        dstb[i] = (uint32_t)(m * 32 + ((c ^ (m & 7)) << 2)) * 4;
    }

    int pa[4], pb[4];
    #pragma unroll
    for (int mf = 0; mf < 4; ++mf) pa[mf] = (wm + mf * 16 + g) * 32 + r;
    #pragma unroll
    for (int nf = 0; nf < 4; ++nf) pb[nf] = (wn + nf * 8 + g) * 32 + r;

    #pragma unroll
    for (int s = 0; s < STAGES - 1; ++s) {
        if (s < ktiles) {
            const uint32_t ab = smb + (uint32_t)(s * SLOT_WORDS) * 4;
            const uint32_t bb = ab + BM * 32 * 4;
            const int kk = s * BKH;
            #pragma unroll
            for (int i = 0; i < 4; ++i) CP_ASYNC16(ab + dstb[i], srcA[i] + kk);
            #pragma unroll
            for (int i = 0; i < 4; ++i) CP_ASYNC16(bb + dstb[i], srcB[i] + kk);
        }
        CP_COMMIT();
    }

    int slot = 0;
    int rslot = STAGES - 1;
    for (int t = 0; t < ktiles; ++t) {
        CP_WAIT(STAGES - 2);
        __syncthreads();

        {
            const int tn = t + STAGES - 1;
            if (tn < ktiles) {
                const uint32_t ab = smb + (uint32_t)(rslot * SLOT_WORDS) * 4;
                const uint32_t bb = ab + BM * 32 * 4;
                const int kk = tn * BKH;
                #pragma unroll
                for (int i = 0; i < 4; ++i) CP_ASYNC16(ab + dstb[i], srcA[i] + kk);
                #pragma unroll
                for (int i = 0; i < 4; ++i) CP_ASYNC16(bb + dstb[i], srcB[i] + kk);
            }
            CP_COMMIT();
        }

        const uint32_t* as = dyn_smem + slot * SLOT_WORDS;
        const uint32_t* bs = as + BM * 32;

        // 4 slices of k16 (chunk pairs {2s, 2s+1})
        #pragma unroll
        for (int s = 0; s < 4; ++s) {
            uint32_t af[4][4], bf[4][2];
            ldfrag(af, bf, as, bs, pa, pb, g, 2 * s);
            #pragma unroll
            for (int mf = 0; mf < 4; ++mf)
                #pragma unroll
                for (int nf = 0; nf < 4; ++nf)
                    mma_f16(acc[mf][nf], af[mf], bf[nf]);
        }

        if (++slot == STAGES) slot = 0;
        if (++rslot == STAGES) rslot = 0;
    }
}

__device__ __forceinline__ void zero_acc(float (&acc)[4][4][4]) {
    #pragma unroll
    for (int i = 0; i < 4; ++i)
        #pragma unroll
        for (int j = 0; j < 4; ++j)
            #pragma unroll
            for (int l = 0; l < 4; ++l) acc[i][j][l] = 0.0f;
}

// f32 epilogue: write acc tile to O[ld = ldo] at (m0, n0)
__device__ __forceinline__ void store_acc(
    float* O, int ldo, int m0, int n0, const float (&acc)[4][4][4])
{
    const int lane = threadIdx.x & 31;
    const int warp = threadIdx.x >> 5;
    const int wm = (warp & 1) * 64;
    const int wn = (warp >> 1) * 32;
    #pragma unroll
    for (int mf = 0; mf < 4; ++mf)
        #pragma unroll
        for (int nf = 0; nf < 4; ++nf) {
            const int rr = m0 + wm + mf * 16 + (lane >> 2);
            const int cc = n0 + wn + nf * 8 + ((lane & 3) << 1);
            *(float2*)(O + (size_t)rr * ldo + cc)       = make_float2(acc[mf][nf][0], acc[mf][nf][1]);
            *(float2*)(O + (size_t)(rr + 8) * ldo + cc) = make_float2(acc[mf][nf][2], acc[mf][nf][3]);
        }
}

// -------------------- device bodies ---------------------------------------
// projection (tf32 engine): z=0 -> q, z=1 -> k, z=2 -> v ; outputs fp16 rn
__device__ __forceinline__ void proj_body(
    int z, int m0, int n0,
    const float* __restrict__ x0, const float* __restrict__ x1, const float* __restrict__ x2,
    const float* __restrict__ bq, const float* __restrict__ bk)
{
    const float* X    = (z == 0) ? x0 : ((z == 1) ? x1 : x2);
    const float* W    = g_wt + (size_t)((z == 0) ? 0 : 1) * DR * DE;
    const float* bias = (z == 0) ? bq : bk;
    __half* O         = (z == 0) ? g_q : ((z == 1) ? g_k : g_v);
    const float scale = (z == 0) ? 0.04419417382415922f : 1.0f;   // 1/sqrt(512)

    float acc[4][4][4];
    zero_acc(acc);
    gemm_core_f32(X, W, DE, DE, DE / BK, m0, n0, acc);

    const int lane = threadIdx.x & 31;
    const int warp = threadIdx.x >> 5;
    const int wm = (warp & 1) * 64;
    const int wn = (warp >> 1) * 32;
    #pragma unroll
    for (int mf = 0; mf < 4; ++mf)
        #pragma unroll
        for (int nf = 0; nf < 4; ++nf) {
            const int rr = m0 + wm + mf * 16 + (lane >> 2);
            const int cc = n0 + wn + nf * 8 + ((lane & 3) << 1);
            const float b0 = bias[cc], b1 = bias[cc + 1];
            *(__half2*)(O + (size_t)rr * DR + cc) =
                __floats2half2_rn((acc[mf][nf][0] + b0) * scale,
                                  (acc[mf][nf][1] + b1) * scale);
            *(__half2*)(O + (size_t)(rr + 8) * DR + cc) =
                __floats2half2_rn((acc[mf][nf][2] + b0) * scale,
                                  (acc[mf][nf][3] + b1) * scale);
        }
}

// scores (fp16 engine): S = Q K^T (f32 out)
__device__ __forceinline__ void scores_body(int b, int m0, int n0)
{
    const __half* Q  = g_q + (size_t)b * N_ * DR;
    const __half* Km = g_k + (size_t)b * N_ * DR;
    float* S         = g_s + (size_t)b * N_ * N_;

    float acc[4][4][4];
    zero_acc(acc);
    gemm_core_h(Q, Km, DR, DR, DR / BKH, m0, n0, acc);
    store_acc(S, N_, m0, n0, acc);
}

// V transpose ([t][d] -> [d][t], fp16)
__device__ __forceinline__ void transv_body(int b, int t0, int d0)
{
    __shared__ __half t[32][33];
    const __half* I = g_v  + (size_t)b * N_ * DR;
    __half*       O = g_vt + (size_t)b * DR * N_;
    const int tx = threadIdx.x & 31, ty = threadIdx.x >> 5;
    #pragma unroll
    for (int i = 0; i < 4; ++i)
        t[ty + 8 * i][tx] = I[(size_t)(t0 + ty + 8 * i) * DR + d0 + tx];
    __syncthreads();
    #pragma unroll
    for (int i = 0; i < 4; ++i)
        O[(size_t)(d0 + ty + 8 * i) * N_ + t0 + tx] = t[tx][ty + 8 * i];
}

// ---- softmax pieces ----
__device__ __forceinline__ float fast_exp(float x) {
    float t = fmaxf(x * 1.4426950408889634f, -126.0f);
    float fi = floorf(t);
    float f = t - fi;
    float p = fmaf(0.00015403530393381608f, f, 0.0013333558146428443f);
    p = fmaf(p, f, 0.009618129107628477f);
    p = fmaf(p, f, 0.05550410866482158f);
    p = fmaf(p, f, 0.24022650695910072f);
    p = fmaf(p, f, 0.6931471805599453f);
    p = fmaf(p, f, 1.0f);
    return p * __int_as_float((uint32_t)((int)fi + 127) << 23);
}
__device__ __forceinline__ float brmax(float v) {
    __shared__ float sm[8];
    #pragma unroll
    for (int o = 16; o > 0; o >>= 1) v = fmaxf(v, __shfl_xor_sync(0xffffffffu, v, o));
    if ((threadIdx.x & 31) == 0) sm[threadIdx.x >> 5] = v;
    __syncthreads();
    v = sm[0];
    #pragma unroll
    for (int i = 1; i < 8; ++i) v = fmaxf(v, sm[i]);
    __syncthreads();
    return v;
}
__device__ __forceinline__ float brsum(float v) {
    __shared__ float sm2[8];
    #pragma unroll
    for (int o = 16; o > 0; o >>= 1) v += __shfl_xor_sync(0xffffffffu, v, o);
    if ((threadIdx.x & 31) == 0) sm2[threadIdx.x >> 5] = v;
    __syncthreads();
    v = sm2[0];
    #pragma unroll
    for (int i = 1; i < 8; ++i) v += sm2[i];
    __syncthreads();
    return v;
}

// causal row softmax: reads S (f32), writes P (fp16 rn) to g_p.
// rows < 1024 only touch cols [0,1024): out reads cols <= m0+127 and
// ceil128(valid) <= 1024 for those rows (g_p is zero-initialized .bss).
__device__ __forceinline__ void softmax_body(int row)
{
    const int rr  = row & (N_ - 1);
    const float* S = g_s + (size_t)row * N_;
    __half* P      = g_p + (size_t)row * N_;
    const int tid = threadIdx.x;
    const int valid = rr + 1;
    const int nchunk = (rr >= 1024) ? 2 : 1;

    float v[8];
    float lmax = -3.402823466e38f;
    for (int i = 0; i < nchunk; ++i) {
        const int c = (tid + i * 256) << 2;
        float4 f = *(const float4*)(S + c);
        v[i * 4 + 0] = (c + 0 < valid) ? f.x : -3.402823466e38f;
        v[i * 4 + 1] = (c + 1 < valid) ? f.y : -3.402823466e38f;
        v[i * 4 + 2] = (c + 2 < valid) ? f.z : -3.402823466e38f;
        v[i * 4 + 3] = (c + 3 < valid) ? f.w : -3.402823466e38f;
        lmax = fmaxf(lmax, fmaxf(fmaxf(v[i*4], v[i*4+1]), fmaxf(v[i*4+2], v[i*4+3])));
    }
    const float m = brmax(lmax);

    float lsum = 0.0f;
    for (int i = 0; i < nchunk * 4; ++i) {
        const int c = ((tid + (i >> 2) * 256) << 2) + (i & 3);
        float e = (c < valid) ? fast_exp(v[i] - m) : 0.0f;
        v[i] = e;
        lsum += e;
    }
    const float inv = 1.0f / brsum(lsum);

    for (int i = 0; i < nchunk; ++i) {
        const int c = (tid + i * 256) << 2;
        *(__half2*)(P + c)     = __floats2half2_rn(v[i*4 + 0] * inv, v[i*4 + 1] * inv);
        *(__half2*)(P + c + 2) = __floats2half2_rn(v[i*4 + 2] * inv, v[i*4 + 3] * inv);
    }
}

// -------------------- kernels ---------------------------------------------
// W transpose ([k][n] -> [n][k], rna tf32 f32 out — proj B operand)
__global__ void __launch_bounds__(256) trans_w(
    const float* __restrict__ Wq, const float* __restrict__ Wk)
{
    __shared__ float t[32][33];
    const int w = blockIdx.z;
    const float* W = w ? Wk : Wq;
    float* O = g_wt + (size_t)w * DR * DE;
    const int n0 = blockIdx.x * 32, k0 = blockIdx.y * 32;
    const int tx = threadIdx.x & 31, ty = threadIdx.x >> 5;
    #pragma unroll
    for (int i = 0; i < 4; ++i)
        t[ty + 8 * i][tx] = W[(size_t)(k0 + ty + 8 * i) * DR + n0 + tx];
    __syncthreads();
    #pragma unroll
    for (int i = 0; i < 4; ++i)
        O[(size_t)(n0 + ty + 8 * i) * DE + k0 + tx] = rnd_tf(t[tx][ty + 8 * i]);
}

// proj for q and k only (z = blockIdx.z in {0,1})
__global__ void __launch_bounds__(256, 2) proj_qk_kernel(
    const float* __restrict__ x0, const float* __restrict__ x1,
    const float* __restrict__ bq, const float* __restrict__ bk)
{
    proj_body(blockIdx.z, blockIdx.y * BM, blockIdx.x * BN, x0, x1, nullptr, bq, bk);
}

// fused: proj_v (first 512 blocks, tf32 engine) || scores (next 2048, fp16)
#define PV_BLOCKS 512
__global__ void __launch_bounds__(256, 2) fused_sv_kernel(
    const float* __restrict__ x2,
    const float* __restrict__ bq, const float* __restrict__ bk)
{
    const int bid = blockIdx.x;
    if (bid < PV_BLOCKS) {
        const int m0 = (bid >> 2) * BM;
        const int n0 = (bid & 3) * BN;
        proj_body(2, m0, n0, nullptr, nullptr, x2, bq, bk);
    } else {
        const int t = bid - PV_BLOCKS;         // 0..2047
        const int b = t >> 8;
        const int r = t & 255;
        const int m0 = (r >> 4) * BM;
        const int n0 = (r & 15) * BN;
        if (n0 > m0) return;                   // above diagonal: masked by softmax
        scores_body(b, m0, n0);
    }
}

// fused: softmax (first 16384 blocks) || V transpose (next 8192 blocks)
#define SM_BLOCKS (B_ * N_)
__global__ void __launch_bounds__(256) fused_smtv_kernel()
{
    const int bid = blockIdx.x;
    if (bid < SM_BLOCKS) {
        softmax_body(bid);
    } else {
        const int t = bid - SM_BLOCKS;
        const int t0 = (t & 63) * 32;
        const int d0 = ((t >> 6) & 15) * 32;
        const int b  = t >> 10;
        transv_body(b, t0, d0);
    }
}

// out = P @ V (fp16 engine) with causal k truncation
__global__ void __launch_bounds__(256, 2) out_kernel(float* __restrict__ out)
{
    const int b  = blockIdx.z;
    const int m0 = blockIdx.y * BM;
    const int n0 = blockIdx.x * BN;

    const __half* P  = g_p  + (size_t)b * N_ * N_;
    const __half* Vt = g_vt + (size_t)b * DR * N_;
    const int ktiles = (m0 + BM) / BKH;   // cols > m0+127 are all zero after softmax

    float acc[4][4][4];
    zero_acc(acc);
    gemm_core_h(P, Vt, N_, N_, ktiles, m0, n0, acc);
    store_acc(out + (size_t)b * N_ * DR, DR, m0, n0, acc);
}

// -------------------- launch ----------------------------------------------
extern "C" void kernel_launch(void* const* d_in, const int* in_sizes, int n_in,
                              void* d_out, int out_size)
{
    (void)in_sizes; (void)n_in; (void)out_size;
    const float* x0 = (const float*)d_in[0];
    const float* x1 = (const float*)d_in[1];
    const float* x2 = (const float*)d_in[2];
    const float* Wq = (const float*)d_in[3];
    const float* bq = (const float*)d_in[4];
    const float* Wk = (const float*)d_in[5];
    const float* bk = (const float*)d_in[6];
    float* out = (float*)d_out;

    static bool attr_done = false;
    if (!attr_done) {
        cudaFuncSetAttribute(proj_qk_kernel,  cudaFuncAttributeMaxDynamicSharedMemorySize, SMEM_GEMM);
        cudaFuncSetAttribute(fused_sv_kernel, cudaFuncAttributeMaxDynamicSharedMemorySize, SMEM_GEMM);
        cudaFuncSetAttribute(out_kernel,      cudaFuncAttributeMaxDynamicSharedMemorySize, SMEM_GEMM);
        attr_done = true;
    }

    dim3 blk(256);
    trans_w<<<dim3(DR / 32, DE / 32, 2), blk>>>(Wq, Wk);
    proj_qk_kernel<<<dim3(DR / BN, (B_ * N_) / BM, 2), blk, SMEM_GEMM>>>(x0, x1, bq, bk);
    fused_sv_kernel<<<dim3(PV_BLOCKS + 2048), blk, SMEM_GEMM>>>(x2, bq, bk);
    fused_smtv_kernel<<<dim3(SM_BLOCKS + 8192), blk>>>();
    out_kernel<<<dim3(DR / BN, N_ / BM, B_), blk, SMEM_GEMM>>>(out);
}